// round 2
// baseline (speedup 1.0000x reference)
#include <cuda_runtime.h>

#define Bn 128
#define Ln 256
#define Dn 512
#define Hn 1024
#define BH (Bn*Hn)      // 131072
#define KSPLIT 8

// scratch (device globals: no allocations allowed)
__device__ float g_xp[(size_t)Ln*BH];   // (L,B,H) pre-activations x@Wx + bx + bh
__device__ float g_hs[(size_t)Ln*BH];   // hidden states per step
__device__ float g_h[2][BH];            // ping-pong h
__device__ float g_c[BH];               // cell state
__device__ float g_zp[KSPLIT][BH];      // K-split partial sums of h@Wh

// ---------- packed f32x2 helpers (Blackwell) ----------
__device__ __forceinline__ unsigned long long pk2(float lo, float hi) {
    unsigned long long r;
    asm("mov.b64 %0, {%1,%2};" : "=l"(r) : "f"(lo), "f"(hi));
    return r;
}
__device__ __forceinline__ void upk2(unsigned long long v, float& lo, float& hi) {
    asm("mov.b64 {%0,%1}, %2;" : "=f"(lo), "=f"(hi) : "l"(v));
}
__device__ __forceinline__ unsigned long long ffma2(unsigned long long a,
                                                    unsigned long long b,
                                                    unsigned long long c) {
    unsigned long long d;
    asm("fma.rn.f32x2 %0, %1, %2, %3;" : "=l"(d) : "l"(a), "l"(b), "l"(c));
    return d;
}

// ---------- init: zero h[0] and c ----------
__global__ void k_init() {
    int i = blockIdx.x * blockDim.x + threadIdx.x;   // 32768 float4 slots
    float4 z = make_float4(0.f, 0.f, 0.f, 0.f);
    ((float4*)g_h[0])[i] = z;
    ((float4*)g_c)[i]    = z;
}

// ---------- xp = x @ Wx + (bx + bh), layout (L,B,H), m = l*B + b ----------
// BM=128, BN=128, BK=16, 256 threads, 8x8 per-thread tile, f32x2 FMAs
__global__ void __launch_bounds__(256) k_xp(const float* __restrict__ x,
                                            const float* __restrict__ Wx,
                                            const float* __restrict__ bx,
                                            const float* __restrict__ bh) {
    __shared__ float As[16][132];   // padded to reduce STS bank conflicts
    __shared__ float Bs[16][128];

    const int tid = threadIdx.x;
    const int nb = blockIdx.x;      // 0..7   (N blocks of 128)
    const int mb = blockIdx.y;      // 0..255 (M blocks of 128)
    const int ty = tid >> 4;        // 0..15
    const int tx = tid & 15;        // 0..15
    const int m0 = ty * 8;
    const int n0 = tx * 8;

    unsigned long long acc[8][4];
#pragma unroll
    for (int i = 0; i < 8; i++)
#pragma unroll
        for (int j = 0; j < 4; j++) acc[i][j] = 0ULL;

    for (int kt = 0; kt < Dn / 16; kt++) {
        const int kb = kt * 16;
        // load A tile (128 rows x 16 k), transposed store
#pragma unroll
        for (int p = 0; p < 2; p++) {
            int s = tid + p * 256;       // 512 float4 slots
            int row = s >> 2, kq = s & 3;
            int gm = mb * 128 + row;     // m = l*B + b
            int bidx = gm & 127, lidx = gm >> 7;
            float4 v = *(const float4*)(x + ((size_t)bidx * Ln + lidx) * Dn + kb + kq * 4);
            As[kq * 4 + 0][row] = v.x;
            As[kq * 4 + 1][row] = v.y;
            As[kq * 4 + 2][row] = v.z;
            As[kq * 4 + 3][row] = v.w;
        }
        // load B tile (16 k x 128 n)
#pragma unroll
        for (int p = 0; p < 2; p++) {
            int s = tid + p * 256;
            int kr = s >> 5, c4 = s & 31;
            *(float4*)&Bs[kr][c4 * 4] =
                *(const float4*)(Wx + (size_t)(kb + kr) * Hn + nb * 128 + c4 * 4);
        }
        __syncthreads();
#pragma unroll
        for (int k = 0; k < 16; k++) {
            float a[8];
            *(float4*)&a[0] = *(const float4*)&As[k][m0];
            *(float4*)&a[4] = *(const float4*)&As[k][m0 + 4];
            const unsigned long long* bsrc = (const unsigned long long*)&Bs[k][n0];
            unsigned long long b2[4];
#pragma unroll
            for (int j = 0; j < 4; j++) b2[j] = bsrc[j];
#pragma unroll
            for (int i = 0; i < 8; i++) {
                unsigned long long a2 = pk2(a[i], a[i]);
#pragma unroll
                for (int j = 0; j < 4; j++) acc[i][j] = ffma2(a2, b2[j], acc[i][j]);
            }
        }
        __syncthreads();
    }

    float bb[8];
#pragma unroll
    for (int j = 0; j < 8; j++) {
        int gn = nb * 128 + n0 + j;
        bb[j] = bx[gn] + bh[gn];
    }
#pragma unroll
    for (int i = 0; i < 8; i++) {
        int gm = mb * 128 + m0 + i;
        float* orow = g_xp + (size_t)gm * Hn + nb * 128 + n0;
#pragma unroll
        for (int j = 0; j < 4; j++) {
            float lo, hi;
            upk2(acc[i][j], lo, hi);
            *(float2*)(orow + 2 * j) = make_float2(lo + bb[2 * j], hi + bb[2 * j + 1]);
        }
    }
}

// ---------- scan step GEMM: z_partial[kz] = h_src @ Wh[kslice] ----------
// tile 128(M=B) x 64(N), K-slice 128, BK=16, 128 threads, 8x8 thread tile
__global__ void __launch_bounds__(128) k_step_gemm(const float* __restrict__ Wh, int l) {
    __shared__ float As[16][132];
    __shared__ float Bs[16][64];

    const float* __restrict__ hsrc = g_h[l & 1];
    const int tid = threadIdx.x;
    const int nb = blockIdx.x;      // 0..15 (N blocks of 64)
    const int kz = blockIdx.y;      // 0..7  (K slices of 128)
    const int ty = tid >> 3;        // 0..15
    const int tx = tid & 7;         // 0..7
    const int m0 = ty * 8;
    const int n0 = tx * 8;

    unsigned long long acc[8][4];
#pragma unroll
    for (int i = 0; i < 8; i++)
#pragma unroll
        for (int j = 0; j < 4; j++) acc[i][j] = 0ULL;

    for (int kt = 0; kt < 8; kt++) {
        const int kb = kz * 128 + kt * 16;
        // A tile: h rows (128 x 16), transposed store
#pragma unroll
        for (int p = 0; p < 4; p++) {
            int s = tid + p * 128;       // 512 float4 slots
            int row = s >> 2, kq = s & 3;
            float4 v = *(const float4*)(hsrc + row * Hn + kb + kq * 4);
            As[kq * 4 + 0][row] = v.x;
            As[kq * 4 + 1][row] = v.y;
            As[kq * 4 + 2][row] = v.z;
            As[kq * 4 + 3][row] = v.w;
        }
        // B tile: Wh (16 x 64)
#pragma unroll
        for (int p = 0; p < 2; p++) {
            int s = tid + p * 128;
            int kr = s >> 4, c4 = s & 15;
            *(float4*)&Bs[kr][c4 * 4] =
                *(const float4*)(Wh + (size_t)(kb + kr) * Hn + nb * 64 + c4 * 4);
        }
        __syncthreads();
#pragma unroll
        for (int k = 0; k < 16; k++) {
            float a[8];
            *(float4*)&a[0] = *(const float4*)&As[k][m0];
            *(float4*)&a[4] = *(const float4*)&As[k][m0 + 4];
            const unsigned long long* bsrc = (const unsigned long long*)&Bs[k][n0];
            unsigned long long b2[4];
#pragma unroll
            for (int j = 0; j < 4; j++) b2[j] = bsrc[j];
#pragma unroll
            for (int i = 0; i < 8; i++) {
                unsigned long long a2 = pk2(a[i], a[i]);
#pragma unroll
                for (int j = 0; j < 4; j++) acc[i][j] = ffma2(a2, b2[j], acc[i][j]);
            }
        }
        __syncthreads();
    }

    float* zp = g_zp[kz];
#pragma unroll
    for (int i = 0; i < 8; i++) {
        float* orow = zp + (m0 + i) * Hn + nb * 64 + n0;
#pragma unroll
        for (int j = 0; j < 4; j++) {
            float lo, hi;
            upk2(acc[i][j], lo, hi);
            *(float2*)(orow + 2 * j) = make_float2(lo, hi);
        }
    }
}

// ---------- scan step activation: reduce K-split, cell update ----------
__device__ __forceinline__ float act1(float z, float& c) {
    float sg = 1.0f / (1.0f + expf(-z));
    float g = tanhf(z);
    c = sg * (c + g);                 // sg*c + sg*g
    return sg * tanhf(c);
}

__global__ void __launch_bounds__(256) k_step_act(int l) {
    int i4 = blockIdx.x * blockDim.x + threadIdx.x;   // 32768 float4 slots
    float4 z = ((const float4*)g_zp[0])[i4];
#pragma unroll
    for (int ks = 1; ks < KSPLIT; ks++) {
        float4 t = ((const float4*)g_zp[ks])[i4];
        z.x += t.x; z.y += t.y; z.z += t.z; z.w += t.w;
    }
    float4 xp = ((const float4*)g_xp)[(size_t)l * (BH / 4) + i4];
    z.x += xp.x; z.y += xp.y; z.z += xp.z; z.w += xp.w;

    float4 c = ((const float4*)g_c)[i4];
    float4 hn;
    hn.x = act1(z.x, c.x);
    hn.y = act1(z.y, c.y);
    hn.z = act1(z.z, c.z);
    hn.w = act1(z.w, c.w);

    ((float4*)g_c)[i4] = c;
    ((float4*)g_h[(l + 1) & 1])[i4] = hn;
    ((float4*)g_hs)[(size_t)l * (BH / 4) + i4] = hn;
}

// ---------- output projection + mask: one warp per (b,l) row ----------
__global__ void __launch_bounds__(256) k_out(const float* __restrict__ Wo,
                                             const float* __restrict__ bo,
                                             const int* __restrict__ slen,
                                             float* __restrict__ out) {
    int gw = (blockIdx.x * 256 + threadIdx.x) >> 5;   // 0..32767
    int lane = threadIdx.x & 31;
    int b = gw >> 8;
    int l = gw & 255;
    const float* hrow = g_hs + ((size_t)l * Bn + b) * Hn;

    float a0 = 0.f, a1 = 0.f;
    for (int h0 = lane * 4; h0 < Hn; h0 += 128) {
        float4 v  = *(const float4*)(hrow + h0);
        float4 w0 = *(const float4*)(Wo + 2 * h0);       // (h0,o0) (h0,o1) (h0+1,o0) (h0+1,o1)
        float4 w1 = *(const float4*)(Wo + 2 * h0 + 4);
        a0 += v.x * w0.x + v.y * w0.z + v.z * w1.x + v.w * w1.z;
        a1 += v.x * w0.y + v.y * w0.w + v.z * w1.y + v.w * w1.w;
    }
#pragma unroll
    for (int off = 16; off; off >>= 1) {
        a0 += __shfl_xor_sync(0xffffffffu, a0, off);
        a1 += __shfl_xor_sync(0xffffffffu, a1, off);
    }
    if (lane == 0) {
        float o0 = 1.f / (1.f + expf(-(a0 + bo[0])));
        float o1 = 1.f / (1.f + expf(-(a1 + bo[1])));
        if (l > slen[b]) { o0 = 0.f; o1 = 1.f; }
        out[2 * gw + 0] = o0;    // gw = b*L + l  matches output row order
        out[2 * gw + 1] = o1;
    }
}

extern "C" void kernel_launch(void* const* d_in, const int* in_sizes, int n_in,
                              void* d_out, int out_size) {
    const float* x    = (const float*)d_in[0];
    const int*   slen = (const int*)  d_in[1];
    const float* Wh   = (const float*)d_in[2];
    const float* bh   = (const float*)d_in[3];
    const float* Wx   = (const float*)d_in[4];
    const float* bx   = (const float*)d_in[5];
    const float* Wo   = (const float*)d_in[6];
    const float* bo   = (const float*)d_in[7];
    float* out = (float*)d_out;

    k_init<<<128, 256>>>();
    k_xp<<<dim3(8, 256), 256>>>(x, Wx, bx, bh);
    for (int l = 0; l < Ln; l++) {
        k_step_gemm<<<dim3(16, 8), 128>>>(Wh, l);
        k_step_act<<<128, 256>>>(l);
    }
    k_out<<<4096, 256>>>(Wo, bo, slen, out);
}

// round 3
// speedup vs baseline: 1.1127x; 1.1127x over previous
#include <cuda_runtime.h>

#define Bn 128
#define Ln 256
#define Dn 512
#define Hn 1024
#define BH (Bn*Hn)      // 131072
#define KSPLIT 8
#define NCTA 128

// scratch (device globals: no allocations allowed)
__device__ float g_xp[(size_t)Ln*BH];   // (L,B,H) pre-activations x@Wx + bx + bh
__device__ float g_hs[(size_t)Ln*BH];   // hidden states per step
__device__ float g_h[2][BH];            // ping-pong h
__device__ float g_zp[KSPLIT][BH];      // K-split partial sums of h@Wh
__device__ unsigned g_count;            // barrier arrive counter (returns to 0)
__device__ unsigned g_phase;            // barrier generation (monotonic)

// ---------- packed f32x2 helpers (Blackwell) ----------
__device__ __forceinline__ unsigned long long pk2(float lo, float hi) {
    unsigned long long r;
    asm("mov.b64 %0, {%1,%2};" : "=l"(r) : "f"(lo), "f"(hi));
    return r;
}
__device__ __forceinline__ void upk2(unsigned long long v, float& lo, float& hi) {
    asm("mov.b64 {%0,%1}, %2;" : "=f"(lo), "=f"(hi) : "l"(v));
}
__device__ __forceinline__ unsigned long long ffma2(unsigned long long a,
                                                    unsigned long long b,
                                                    unsigned long long c) {
    unsigned long long d;
    asm("fma.rn.f32x2 %0, %1, %2, %3;" : "=l"(d) : "l"(a), "l"(b), "l"(c));
    return d;
}

// ---------- software grid barrier (replay-safe: count self-resets) ----------
__device__ __forceinline__ void grid_sync() {
    __syncthreads();
    if (threadIdx.x == 0) {
        __threadfence();                                   // release prior writes
        unsigned ph = *(volatile unsigned*)&g_phase;       // read BEFORE arriving
        if (atomicAdd(&g_count, 1) == NCTA - 1) {
            atomicExch(&g_count, 0);                       // reset for next use
            __threadfence();
            atomicAdd(&g_phase, 1);                        // release everyone
        } else {
            while (*(volatile unsigned*)&g_phase == ph) { __nanosleep(64); }
        }
        __threadfence();                                   // acquire
    }
    __syncthreads();
}

// ---------- xp = x @ Wx + (bx + bh), layout (L,B,H), m = l*B + b ----------
__global__ void __launch_bounds__(256) k_xp(const float* __restrict__ x,
                                            const float* __restrict__ Wx,
                                            const float* __restrict__ bx,
                                            const float* __restrict__ bh) {
    __shared__ float As[16][132];
    __shared__ float Bs[16][128];

    const int tid = threadIdx.x;
    const int nb = blockIdx.x;      // 0..7
    const int mb = blockIdx.y;      // 0..255
    const int ty = tid >> 4;
    const int tx = tid & 15;
    const int m0 = ty * 8;
    const int n0 = tx * 8;

    unsigned long long acc[8][4];
#pragma unroll
    for (int i = 0; i < 8; i++)
#pragma unroll
        for (int j = 0; j < 4; j++) acc[i][j] = 0ULL;

    for (int kt = 0; kt < Dn / 16; kt++) {
        const int kb = kt * 16;
#pragma unroll
        for (int p = 0; p < 2; p++) {
            int s = tid + p * 256;
            int row = s >> 2, kq = s & 3;
            int gm = mb * 128 + row;
            int bidx = gm & 127, lidx = gm >> 7;
            float4 v = *(const float4*)(x + ((size_t)bidx * Ln + lidx) * Dn + kb + kq * 4);
            As[kq * 4 + 0][row] = v.x;
            As[kq * 4 + 1][row] = v.y;
            As[kq * 4 + 2][row] = v.z;
            As[kq * 4 + 3][row] = v.w;
        }
#pragma unroll
        for (int p = 0; p < 2; p++) {
            int s = tid + p * 256;
            int kr = s >> 5, c4 = s & 31;
            *(float4*)&Bs[kr][c4 * 4] =
                *(const float4*)(Wx + (size_t)(kb + kr) * Hn + nb * 128 + c4 * 4);
        }
        __syncthreads();
#pragma unroll
        for (int k = 0; k < 16; k++) {
            float a[8];
            *(float4*)&a[0] = *(const float4*)&As[k][m0];
            *(float4*)&a[4] = *(const float4*)&As[k][m0 + 4];
            const unsigned long long* bsrc = (const unsigned long long*)&Bs[k][n0];
            unsigned long long b2[4];
#pragma unroll
            for (int j = 0; j < 4; j++) b2[j] = bsrc[j];
#pragma unroll
            for (int i = 0; i < 8; i++) {
                unsigned long long a2 = pk2(a[i], a[i]);
#pragma unroll
                for (int j = 0; j < 4; j++) acc[i][j] = ffma2(a2, b2[j], acc[i][j]);
            }
        }
        __syncthreads();
    }

    float bb[8];
#pragma unroll
    for (int j = 0; j < 8; j++) {
        int gn = nb * 128 + n0 + j;
        bb[j] = bx[gn] + bh[gn];
    }
#pragma unroll
    for (int i = 0; i < 8; i++) {
        int gm = mb * 128 + m0 + i;
        float* orow = g_xp + (size_t)gm * Hn + nb * 128 + n0;
#pragma unroll
        for (int j = 0; j < 4; j++) {
            float lo, hi;
            upk2(acc[i][j], lo, hi);
            *(float2*)(orow + 2 * j) = make_float2(lo + bb[2 * j], hi + bb[2 * j + 1]);
        }
    }
}

// ---------- activation helper (accurate path) ----------
__device__ __forceinline__ float act1(float z, float& c) {
    float sg = 1.0f / (1.0f + expf(-z));
    float g = tanhf(z);
    c = sg * (c + g);                 // sg*c + sg*g
    return sg * tanhf(c);
}

// ---------- persistent fused scan kernel ----------
// 128 CTAs = 16 N-tiles x 8 K-slices. Wh slice lives in SMEM for all 256 steps.
// Phase A: partial z = h[:,kslice] @ Wh_slice  -> g_zp[kz]
// Phase B: CTA b-row ownership; reduce 8 partials + xp, cell update (c in regs)
__global__ void __launch_bounds__(256, 1) k_scan(const float* __restrict__ Wh) {
    __shared__ float Whs[128][64];   // 32 KB persistent Wh slice
    __shared__ float As[16][132];    // h chunk staging (transposed)

    const int tid = threadIdx.x;
    const int cta = blockIdx.x;      // 0..127
    const int nb = cta & 15;         // N tile (64 cols)
    const int kz = cta >> 4;         // K slice (128 rows)

    // preload Wh slice [kz*128 : +128) x [nb*64 : +64)
    for (int s = tid; s < 128 * 16; s += 256) {
        int r = s >> 4, c4 = s & 15;
        *(float4*)&Whs[r][c4 * 4] =
            *(const float4*)(Wh + (size_t)(kz * 128 + r) * Hn + nb * 64 + c4 * 4);
    }
    // zero h[0] (this CTA's 1/128 share)
    ((float4*)g_h[0])[cta * 256 + tid] = make_float4(0.f, 0.f, 0.f, 0.f);
    // cell state for row b=cta, cols tid*4..+4 lives in registers
    float4 c4 = make_float4(0.f, 0.f, 0.f, 0.f);

    const int ty = tid >> 4, tx = tid & 15;
    const int m0 = ty * 8, n0 = tx * 4;

    grid_sync();

    for (int l = 0; l < Ln; l++) {
        // ---- phase A: GEMM partial ----
        const float* __restrict__ hsrc = g_h[l & 1];
        unsigned long long acc[8][2];
#pragma unroll
        for (int i = 0; i < 8; i++) { acc[i][0] = 0ULL; acc[i][1] = 0ULL; }

        for (int kt = 0; kt < 8; kt++) {
            const int kb = kz * 128 + kt * 16;
#pragma unroll
            for (int p = 0; p < 2; p++) {
                int s = tid + p * 256;           // 512 float4 slots
                int row = s >> 2, q = s & 3;
                float4 v = __ldcg((const float4*)(hsrc + row * Hn + kb + q * 4));
                As[q * 4 + 0][row] = v.x;
                As[q * 4 + 1][row] = v.y;
                As[q * 4 + 2][row] = v.z;
                As[q * 4 + 3][row] = v.w;
            }
            __syncthreads();
#pragma unroll
            for (int k = 0; k < 16; k++) {
                float a[8];
                *(float4*)&a[0] = *(const float4*)&As[k][m0];
                *(float4*)&a[4] = *(const float4*)&As[k][m0 + 4];
                unsigned long long b0 = *(const unsigned long long*)&Whs[kt * 16 + k][n0];
                unsigned long long b1 = *(const unsigned long long*)&Whs[kt * 16 + k][n0 + 2];
#pragma unroll
                for (int i = 0; i < 8; i++) {
                    unsigned long long a2 = pk2(a[i], a[i]);
                    acc[i][0] = ffma2(a2, b0, acc[i][0]);
                    acc[i][1] = ffma2(a2, b1, acc[i][1]);
                }
            }
            __syncthreads();
        }
        // write partial tile to g_zp[kz]
        {
            float* zp = g_zp[kz];
#pragma unroll
            for (int i = 0; i < 8; i++) {
                float lo0, hi0, lo1, hi1;
                upk2(acc[i][0], lo0, hi0);
                upk2(acc[i][1], lo1, hi1);
                *(float4*)(zp + (size_t)(m0 + i) * Hn + nb * 64 + n0) =
                    make_float4(lo0, hi0, lo1, hi1);
            }
        }
        grid_sync();

        // ---- phase B: reduce + activate (row b = cta) ----
        float4 z4 = __ldcg((const float4*)(g_zp[0] + (size_t)cta * Hn) + tid);
#pragma unroll
        for (int ks = 1; ks < KSPLIT; ks++) {
            float4 t = __ldcg((const float4*)(g_zp[ks] + (size_t)cta * Hn) + tid);
            z4.x += t.x; z4.y += t.y; z4.z += t.z; z4.w += t.w;
        }
        {
            float4 xp = ((const float4*)(g_xp + (size_t)l * BH + (size_t)cta * Hn))[tid];
            z4.x += xp.x; z4.y += xp.y; z4.z += xp.z; z4.w += xp.w;
        }
        float4 hn;
        hn.x = act1(z4.x, c4.x);
        hn.y = act1(z4.y, c4.y);
        hn.z = act1(z4.z, c4.z);
        hn.w = act1(z4.w, c4.w);

        int i4 = cta * 256 + tid;
        ((float4*)g_h[(l + 1) & 1])[i4] = hn;
        ((float4*)(g_hs + (size_t)l * BH))[i4] = hn;

        grid_sync();
    }
}

// ---------- output projection + mask: one warp per (b,l) row ----------
__global__ void __launch_bounds__(256) k_out(const float* __restrict__ Wo,
                                             const float* __restrict__ bo,
                                             const int* __restrict__ slen,
                                             float* __restrict__ out) {
    int gw = (blockIdx.x * 256 + threadIdx.x) >> 5;   // 0..32767
    int lane = threadIdx.x & 31;
    int b = gw >> 8;
    int l = gw & 255;
    const float* hrow = g_hs + ((size_t)l * Bn + b) * Hn;

    float a0 = 0.f, a1 = 0.f;
    for (int h0 = lane * 4; h0 < Hn; h0 += 128) {
        float4 v  = *(const float4*)(hrow + h0);
        float4 w0 = *(const float4*)(Wo + 2 * h0);
        float4 w1 = *(const float4*)(Wo + 2 * h0 + 4);
        a0 += v.x * w0.x + v.y * w0.z + v.z * w1.x + v.w * w1.z;
        a1 += v.x * w0.y + v.y * w0.w + v.z * w1.y + v.w * w1.w;
    }
#pragma unroll
    for (int off = 16; off; off >>= 1) {
        a0 += __shfl_xor_sync(0xffffffffu, a0, off);
        a1 += __shfl_xor_sync(0xffffffffu, a1, off);
    }
    if (lane == 0) {
        float o0 = 1.f / (1.f + expf(-(a0 + bo[0])));
        float o1 = 1.f / (1.f + expf(-(a1 + bo[1])));
        if (l > slen[b]) { o0 = 0.f; o1 = 1.f; }
        out[2 * gw + 0] = o0;
        out[2 * gw + 1] = o1;
    }
}

extern "C" void kernel_launch(void* const* d_in, const int* in_sizes, int n_in,
                              void* d_out, int out_size) {
    const float* x    = (const float*)d_in[0];
    const int*   slen = (const int*)  d_in[1];
    const float* Wh   = (const float*)d_in[2];
    const float* bh   = (const float*)d_in[3];
    const float* Wx   = (const float*)d_in[4];
    const float* bx   = (const float*)d_in[5];
    const float* Wo   = (const float*)d_in[6];
    const float* bo   = (const float*)d_in[7];
    float* out = (float*)d_out;

    k_xp<<<dim3(8, 256), 256>>>(x, Wx, bx, bh);
    k_scan<<<NCTA, 256>>>(Wh);
    k_out<<<4096, 256>>>(Wo, bo, slen, out);
}